// round 7
// baseline (speedup 1.0000x reference)
#include <cuda_runtime.h>
#include <cuda_fp16.h>
#include <cstddef>
#include <cstdint>

#define BATCH 8
#define CH    512
#define TOK   1024
#define HEADS 8
#define HD    64
#define NHEAD (BATCH*HEADS)   // 64
#define GROUPS 32
#define CPG   16

#define QSCALE 0.1803368801111204f   // 0.125 * log2(e)

// ---------------- scratch (__device__ globals; alloc-free rule) -------------
__device__ __align__(16) __half g_nT  [(size_t)BATCH*TOK*CH];    // [b][t][c]
__device__ __align__(16) __half g_wqkv[(size_t)3*CH*CH];         // [och][c]
__device__ __align__(16) __half g_wout[(size_t)CH*CH];           // [och][c]
__device__ __align__(16) __half g_q   [(size_t)NHEAD*TOK*HD];    // [head][t][c]  (x QSCALE)
__device__ __align__(16) __half g_k   [(size_t)NHEAD*TOK*HD];    // [head][s][c]
__device__ __align__(16) __half g_v   [(size_t)NHEAD*HD*TOK];    // [head][c][s]
__device__ __align__(16) __half g_netT[(size_t)BATCH*TOK*CH];    // [b][t][c]

// ---------------- helpers ---------------------------------------------------
__device__ __forceinline__ void mma_f16(float* c, const uint32_t* a, const uint32_t* b)
{
    asm volatile(
        "mma.sync.aligned.m16n8k16.row.col.f32.f16.f16.f32 "
        "{%0,%1,%2,%3},{%4,%5,%6,%7},{%8,%9},{%0,%1,%2,%3};"
        : "+f"(c[0]), "+f"(c[1]), "+f"(c[2]), "+f"(c[3])
        : "r"(a[0]), "r"(a[1]), "r"(a[2]), "r"(a[3]), "r"(b[0]), "r"(b[1]));
}

// P = 2^(half2(lo,hi) - 2): cvt f32x2->f16x2, shift (cancels in O/l), packed ex2
__device__ __forceinline__ uint32_t h2p(float lo, float hi)
{
    uint32_t d;
    asm("cvt.rn.f16x2.f32 %0, %1, %2;" : "=r"(d) : "f"(hi), "f"(lo));
    asm("add.f16x2 %0, %0, %1;" : "+r"(d) : "r"(0xC000C000u));   // (-2,-2)
    asm("ex2.approx.f16x2 %0, %0;" : "+r"(d));
    return d;
}

__device__ __forceinline__ void cp16(void* s, const void* g)
{
    uint32_t sa = (uint32_t)__cvta_generic_to_shared(s);
    asm volatile("cp.async.cg.shared.global [%0], [%1], 16;\n" :: "r"(sa), "l"(g));
}
#define CP_COMMIT() asm volatile("cp.async.commit_group;\n" ::: "memory")
#define CP_WAIT1()  asm volatile("cp.async.wait_group 1;\n" ::: "memory")
#define CP_WAIT0()  asm volatile("cp.async.wait_group 0;\n" ::: "memory")

// ---------------------------------------------------------------------------
// Kernel 1: fused prep. Blocks 0..255: GroupNorm -> g_nT (transposed half),
// sync-free transform pass. Blocks 256..1279: weight fp32->fp16 conversion.
// ---------------------------------------------------------------------------
__global__ void prep_kernel(const float* __restrict__ x,
                            const float* __restrict__ w,
                            const float* __restrict__ bb,
                            const float* __restrict__ qkvw,
                            const float* __restrict__ outw)
{
    int tid = threadIdx.x;
    if (blockIdx.x >= 256) {
        int i = (blockIdx.x - 256) * 256 + tid;
        const int N1 = 3*CH*CH/4;
        const int N2 = CH*CH/4;
        if (i < N1) {
            float4 v = *(const float4*)(qkvw + (size_t)i*4);
            __half* d = g_wqkv + (size_t)i*4;
            d[0]=__float2half_rn(v.x); d[1]=__float2half_rn(v.y);
            d[2]=__float2half_rn(v.z); d[3]=__float2half_rn(v.w);
        } else if (i < N1 + N2) {
            int j = i - N1;
            float4 v = *(const float4*)(outw + (size_t)j*4);
            __half* d = g_wout + (size_t)j*4;
            d[0]=__float2half_rn(v.x); d[1]=__float2half_rn(v.y);
            d[2]=__float2half_rn(v.z); d[3]=__float2half_rn(v.w);
        }
        return;
    }

    int blk = blockIdx.x;
    int b = blk >> 5, gg = blk & 31;
    const float* src = x + ((size_t)b*CH + gg*CPG) * TOK;
    const int N = CPG * TOK;   // 16384

    float s = 0.f, ss = 0.f;
    for (int i = tid*4; i < N; i += 256*4) {
        float4 v = *(const float4*)(src + i);
        s  += v.x + v.y + v.z + v.w;
        ss += v.x*v.x + v.y*v.y + v.z*v.z + v.w*v.w;
    }
    for (int o = 16; o; o >>= 1) {
        s  += __shfl_down_sync(~0u, s,  o);
        ss += __shfl_down_sync(~0u, ss, o);
    }
    __shared__ float shs[8], shq[8];
    __shared__ float f_mu, f_rstd;
    if ((tid & 31) == 0) { shs[tid>>5] = s; shq[tid>>5] = ss; }
    __syncthreads();
    if (tid == 0) {
        float ts = 0.f, tq = 0.f;
        #pragma unroll
        for (int i = 0; i < 8; i++) { ts += shs[i]; tq += shq[i]; }
        float mu  = ts / N;
        f_mu = mu;
        f_rstd = rsqrtf(tq / N - mu*mu + 1e-5f);
    }
    __syncthreads();
    float mu = f_mu, rstd = f_rstd;

    // sync-free normalize+transpose: thread owns (token lane, c-quad)
    int tl = tid >> 2;            // 0..63 token within 64-chunk
    int c4 = (tid & 3) * 4;       // c quad 0,4,8,12
    float scw[4], scb[4];
    #pragma unroll
    for (int i = 0; i < 4; i++) {
        scw[i] = w[gg*CPG + c4 + i] * rstd;
        scb[i] = bb[gg*CPG + c4 + i] - mu * scw[i];
    }
    const float* s0 = src + (size_t)c4*TOK;
    #pragma unroll 4
    for (int t0 = 0; t0 < TOK; t0 += 64) {
        int t = t0 + tl;
        float v0 = s0[t];
        float v1 = s0[TOK + t];
        float v2 = s0[2*TOK + t];
        float v3 = s0[3*TOK + t];
        __half2 h0 = __floats2half2_rn(v0*scw[0]+scb[0], v1*scw[1]+scb[1]);
        __half2 h1 = __floats2half2_rn(v2*scw[2]+scb[2], v3*scw[3]+scb[3]);
        __half* dst = g_nT + ((size_t)b*TOK + t)*CH + gg*CPG + c4;
        *(__half2*)(dst)   = h0;
        *(__half2*)(dst+2) = h1;
    }
}

// ---------------------------------------------------------------------------
// Kernel 2: qkv GEMM. C[t][och] = sum_c nT[t][c]*Wqkv[och][c]. 128x128 tile,
// 256 thr / 8 warps, double-buffered cp.async. Epilogue routes q/k/v.
// ---------------------------------------------------------------------------
__global__ void __launch_bounds__(256)
gemm_qkv(const __half* __restrict__ Abase, const __half* __restrict__ Bbase,
         const float* __restrict__ bias)
{
    __shared__ __align__(16) __half As[2][128][40];
    __shared__ __align__(16) __half Bs[2][128][40];

    int bz = blockIdx.z;
    const __half* A = Abase + (size_t)bz*TOK*CH;
    const __half* B = Bbase;

    int m0 = blockIdx.y * 128, n0 = blockIdx.x * 128;
    int tid = threadIdx.x, wid = tid >> 5, lane = tid & 31;
    int g = lane >> 2, tg = lane & 3;
    int wm = wid & 3, wn = wid >> 2;

    int lr = tid >> 2;
    int lc = (tid & 3) * 8;

    cp16(&As[0][lr   ][lc], A + (size_t)(m0+lr   )*CH + lc);
    cp16(&As[0][lr+64][lc], A + (size_t)(m0+lr+64)*CH + lc);
    cp16(&Bs[0][lr   ][lc], B + (size_t)(n0+lr   )*CH + lc);
    cp16(&Bs[0][lr+64][lc], B + (size_t)(n0+lr+64)*CH + lc);
    CP_COMMIT();

    float acc[2][8][4] = {};

    for (int ks = 0; ks < 16; ks++) {
        int buf = ks & 1;
        if (ks + 1 < 16) {
            int k1 = (ks+1) * 32;
            cp16(&As[buf^1][lr   ][lc], A + (size_t)(m0+lr   )*CH + k1 + lc);
            cp16(&As[buf^1][lr+64][lc], A + (size_t)(m0+lr+64)*CH + k1 + lc);
            cp16(&Bs[buf^1][lr   ][lc], B + (size_t)(n0+lr   )*CH + k1 + lc);
            cp16(&Bs[buf^1][lr+64][lc], B + (size_t)(n0+lr+64)*CH + k1 + lc);
            CP_COMMIT();
            CP_WAIT1();
        } else {
            CP_WAIT0();
        }
        __syncthreads();
        #pragma unroll
        for (int kk = 0; kk < 2; kk++) {
            uint32_t af[2][4], bf[8][2];
            int kc = kk*16 + tg*2;
            #pragma unroll
            for (int i = 0; i < 2; i++) {
                int mr = wm*32 + i*16 + g;
                af[i][0] = *(const uint32_t*)&As[buf][mr  ][kc];
                af[i][1] = *(const uint32_t*)&As[buf][mr+8][kc];
                af[i][2] = *(const uint32_t*)&As[buf][mr  ][kc+8];
                af[i][3] = *(const uint32_t*)&As[buf][mr+8][kc+8];
            }
            #pragma unroll
            for (int j = 0; j < 8; j++) {
                int nr = wn*64 + j*8 + g;
                bf[j][0] = *(const uint32_t*)&Bs[buf][nr][kc];
                bf[j][1] = *(const uint32_t*)&Bs[buf][nr][kc+8];
            }
            #pragma unroll
            for (int i = 0; i < 2; i++)
                #pragma unroll
                for (int j = 0; j < 8; j++)
                    mma_f16(acc[i][j], af[i], bf[j]);
        }
        __syncthreads();
    }

    #pragma unroll
    for (int j = 0; j < 8; j++) {
        int n = n0 + wn*64 + j*8 + tg*2;      // och
        float bi0 = bias[n], bi1 = bias[n+1];
        int hh = n / 192, r = n % 192;
        #pragma unroll
        for (int i = 0; i < 2; i++) {
            int t = m0 + wm*32 + i*16 + g;
            float v00 = acc[i][j][0]+bi0, v01 = acc[i][j][1]+bi1;
            float v10 = acc[i][j][2]+bi0, v11 = acc[i][j][3]+bi1;
            size_t hb = (size_t)(bz*HEADS + hh);
            if (r < 64) {
                v00*=QSCALE; v01*=QSCALE; v10*=QSCALE; v11*=QSCALE;
                __half* q = g_q + (hb*TOK)*HD + r;
                *(__half2*)(q + (size_t)t    *HD) = __floats2half2_rn(v00, v01);
                *(__half2*)(q + (size_t)(t+8)*HD) = __floats2half2_rn(v10, v11);
            } else if (r < 128) {
                __half* k = g_k + (hb*TOK)*HD + (r-64);
                *(__half2*)(k + (size_t)t    *HD) = __floats2half2_rn(v00, v01);
                *(__half2*)(k + (size_t)(t+8)*HD) = __floats2half2_rn(v10, v11);
            } else {
                int cc = r - 128;
                __half* v = g_v + (hb*HD + cc)*TOK;
                v[t]         = __float2half_rn(v00);
                v[TOK + t]   = __float2half_rn(v01);
                v[t+8]       = __float2half_rn(v10);
                v[TOK + t+8] = __float2half_rn(v11);
            }
        }
    }
}

// ---------------------------------------------------------------------------
// Kernel 4: out projection. C[och][t] = sum_c Wout[och][c]*netT[t][c]
// + out_b + residual. 64x128 tile, 128 thr / 4 warps (2m x 2n), 512 blocks.
// ---------------------------------------------------------------------------
__global__ void __launch_bounds__(128)
gemm_out(const __half* __restrict__ Abase, const __half* __restrict__ Bbase,
         const float* __restrict__ bias, const float* __restrict__ res,
         float* __restrict__ Cout)
{
    __shared__ __align__(16) __half As[2][64][40];
    __shared__ __align__(16) __half Bs[2][128][40];

    int bz = blockIdx.z;
    const __half* A = Abase;                      // weights [och][c]
    const __half* B = Bbase + (size_t)bz*TOK*CH;  // netT [t][c]

    int m0 = blockIdx.y * 64, n0 = blockIdx.x * 128;
    int tid = threadIdx.x, wid = tid >> 5, lane = tid & 31;
    int g = lane >> 2, tg = lane & 3;
    int wm = wid & 1, wn = wid >> 1;

    int lr = tid >> 2;            // 0..31
    int lc = (tid & 3) * 8;

    cp16(&As[0][lr   ][lc], A + (size_t)(m0+lr   )*CH + lc);
    cp16(&As[0][lr+32][lc], A + (size_t)(m0+lr+32)*CH + lc);
    cp16(&Bs[0][lr   ][lc], B + (size_t)(n0+lr   )*CH + lc);
    cp16(&Bs[0][lr+32][lc], B + (size_t)(n0+lr+32)*CH + lc);
    cp16(&Bs[0][lr+64][lc], B + (size_t)(n0+lr+64)*CH + lc);
    cp16(&Bs[0][lr+96][lc], B + (size_t)(n0+lr+96)*CH + lc);
    CP_COMMIT();

    float acc[2][8][4] = {};

    for (int ks = 0; ks < 16; ks++) {
        int buf = ks & 1;
        if (ks + 1 < 16) {
            int k1 = (ks+1) * 32;
            cp16(&As[buf^1][lr   ][lc], A + (size_t)(m0+lr   )*CH + k1 + lc);
            cp16(&As[buf^1][lr+32][lc], A + (size_t)(m0+lr+32)*CH + k1 + lc);
            cp16(&Bs[buf^1][lr   ][lc], B + (size_t)(n0+lr   )*CH + k1 + lc);
            cp16(&Bs[buf^1][lr+32][lc], B + (size_t)(n0+lr+32)*CH + k1 + lc);
            cp16(&Bs[buf^1][lr+64][lc], B + (size_t)(n0+lr+64)*CH + k1 + lc);
            cp16(&Bs[buf^1][lr+96][lc], B + (size_t)(n0+lr+96)*CH + k1 + lc);
            CP_COMMIT();
            CP_WAIT1();
        } else {
            CP_WAIT0();
        }
        __syncthreads();
        #pragma unroll
        for (int kk = 0; kk < 2; kk++) {
            uint32_t af[2][4], bf[8][2];
            int kc = kk*16 + tg*2;
            #pragma unroll
            for (int i = 0; i < 2; i++) {
                int mr = wm*32 + i*16 + g;
                af[i][0] = *(const uint32_t*)&As[buf][mr  ][kc];
                af[i][1] = *(const uint32_t*)&As[buf][mr+8][kc];
                af[i][2] = *(const uint32_t*)&As[buf][mr  ][kc+8];
                af[i][3] = *(const uint32_t*)&As[buf][mr+8][kc+8];
            }
            #pragma unroll
            for (int j = 0; j < 8; j++) {
                int nr = wn*64 + j*8 + g;
                bf[j][0] = *(const uint32_t*)&Bs[buf][nr][kc];
                bf[j][1] = *(const uint32_t*)&Bs[buf][nr][kc+8];
            }
            #pragma unroll
            for (int i = 0; i < 2; i++)
                #pragma unroll
                for (int j = 0; j < 8; j++)
                    mma_f16(acc[i][j], af[i], bf[j]);
        }
        __syncthreads();
    }

    #pragma unroll
    for (int j = 0; j < 8; j++) {
        int n = n0 + wn*64 + j*8 + tg*2;
        #pragma unroll
        for (int i = 0; i < 2; i++) {
            int m = m0 + wm*32 + i*16 + g;
            float ob0 = bias[m], ob1 = bias[m+8];
            size_t o0 = ((size_t)bz*CH + m)*TOK + n;
            size_t o1 = ((size_t)bz*CH + m+8)*TOK + n;
            float2 r0 = *(const float2*)(res + o0);
            float2 r1 = *(const float2*)(res + o1);
            float2 w0 = { acc[i][j][0]+ob0+r0.x, acc[i][j][1]+ob0+r0.y };
            float2 w1 = { acc[i][j][2]+ob1+r1.x, acc[i][j][3]+ob1+r1.y };
            *(float2*)(Cout + o0) = w0;
            *(float2*)(Cout + o1) = w1;
        }
    }
}

// ---------------------------------------------------------------------------
// Kernel 3: flash attention. Block = (head, 64 q-rows), 128 thr / 4 warps.
// Static-shift softmax fully in f16x2 MUFU; row sums via ones-column MMA.
// K/V double-buffered cp.async.
// ---------------------------------------------------------------------------
__global__ void __launch_bounds__(128) flash_kernel()
{
    int head = blockIdx.y;
    int b = head >> 3, h = head & 7;
    int t0 = blockIdx.x * 64;
    const __half* Qg = g_q + ((size_t)head*TOK + t0)*HD;
    const __half* Kg = g_k + (size_t)head*TOK*HD;
    const __half* Vg = g_v + (size_t)head*HD*TOK;

    __shared__ __align__(16) __half Qs[64][72];
    __shared__ __align__(16) __half Ks[2][64][72];
    __shared__ __align__(16) __half Vs[2][64][72];

    int tid = threadIdx.x, wid = tid >> 5, lane = tid & 31;
    int g = lane >> 2, tg = lane & 3;

    #pragma unroll
    for (int p = 0; p < 4; p++) {
        int u = tid + p*128;
        int r = u >> 3, cg = (u & 7) * 8;
        *(uint4*)&Qs[r][cg] = *(const uint4*)(Qg + (size_t)r*HD + cg);
    }
    #pragma unroll
    for (int p = 0; p < 4; p++) {
        int u = tid + p*128;
        int r = u >> 3, cg = (u & 7) * 8;
        cp16(&Ks[0][r][cg], Kg + (size_t)r*HD + cg);
        cp16(&Vs[0][r][cg], Vg + (size_t)r*TOK + cg);
    }
    CP_COMMIT();
    __syncthreads();

    uint32_t aq[4][4];
    #pragma unroll
    for (int kk = 0; kk < 4; kk++) {
        int mr = wid*16 + g, kc = kk*16 + tg*2;
        aq[kk][0] = *(const uint32_t*)&Qs[mr  ][kc];
        aq[kk][1] = *(const uint32_t*)&Qs[mr+8][kc];
        aq[kk][2] = *(const uint32_t*)&Qs[mr  ][kc+8];
        aq[kk][3] = *(const uint32_t*)&Qs[mr+8][kc+8];
    }

    const uint32_t ones2 = 0x3C003C00u;    // half2(1,1)
    float o[8][4] = {};
    float ol[4] = {};                      // row-sum accumulator (ones column)

    for (int it = 0; it < 16; it++) {
        int buf = it & 1;
        if (it + 1 < 16) {
            int s1 = (it+1)*64;
            #pragma unroll
            for (int p = 0; p < 4; p++) {
                int u = tid + p*128;
                int r = u >> 3, cg = (u & 7) * 8;
                cp16(&Ks[buf^1][r][cg], Kg + (size_t)(s1+r)*HD + cg);
                cp16(&Vs[buf^1][r][cg], Vg + (size_t)r*TOK + s1 + cg);
            }
            CP_COMMIT();
            CP_WAIT1();
        } else {
            CP_WAIT0();
        }
        __syncthreads();

        // S = Q K^T  (log2 domain, pre-scaled)
        float sc[8][4] = {};
        #pragma unroll
        for (int kk = 0; kk < 4; kk++) {
            int kc = kk*16 + tg*2;
            #pragma unroll
            for (int j = 0; j < 8; j++) {
                uint32_t bf[2];
                bf[0] = *(const uint32_t*)&Ks[buf][j*8+g][kc];
                bf[1] = *(const uint32_t*)&Ks[buf][j*8+g][kc+8];
                mma_f16(sc[j], aq[kk], bf);
            }
        }

        // P = 2^(S-2) in packed half2 (shift cancels exactly in O/l)
        uint32_t ph[8][2];
        #pragma unroll
        for (int j = 0; j < 8; j++) {
            ph[j][0] = h2p(sc[j][0], sc[j][1]);   // row g
            ph[j][1] = h2p(sc[j][2], sc[j][3]);   // row g+8
        }

        // O += P V ; ol += P * ones (row sums, same rounding as O)
        #pragma unroll
        for (int i = 0; i < 4; i++) {
            uint32_t ap[4];
            ap[0] = ph[2*i  ][0];
            ap[1] = ph[2*i  ][1];
            ap[2] = ph[2*i+1][0];
            ap[3] = ph[2*i+1][1];
            int kc = i*16 + tg*2;
            #pragma unroll
            for (int jc = 0; jc < 8; jc++) {
                uint32_t bf[2];
                bf[0] = *(const uint32_t*)&Vs[buf][jc*8+g][kc];
                bf[1] = *(const uint32_t*)&Vs[buf][jc*8+g][kc+8];
                mma_f16(o[jc], ap, bf);
            }
            uint32_t bo[2] = { ones2, ones2 };
            mma_f16(ol, ap, bo);
        }
        __syncthreads();
    }

    float inv0 = 1.f / ol[0], inv1 = 1.f / ol[2];
    int t = t0 + wid*16 + g;
    size_t rowbase = (size_t)b*TOK;
    #pragma unroll
    for (int jc = 0; jc < 8; jc++) {
        int cc = h*HD + jc*8 + tg*2;
        *(__half2*)&g_netT[(rowbase + t  )*CH + cc] =
            __floats2half2_rn(o[jc][0]*inv0, o[jc][1]*inv0);
        *(__half2*)&g_netT[(rowbase + t+8)*CH + cc] =
            __floats2half2_rn(o[jc][2]*inv1, o[jc][3]*inv1);
    }
}

// ---------------------------------------------------------------------------
extern "C" void kernel_launch(void* const* d_in, const int* in_sizes, int n_in,
                              void* d_out, int out_size)
{
    const float* x     = (const float*)d_in[0];
    const float* gn_w  = (const float*)d_in[1];
    const float* gn_b  = (const float*)d_in[2];
    const float* qkv_w = (const float*)d_in[3];
    const float* qkv_b = (const float*)d_in[4];
    const float* out_w = (const float*)d_in[5];
    const float* out_b = (const float*)d_in[6];
    float* out = (float*)d_out;

    __half *nT, *wqkv, *wout, *netT;
    cudaGetSymbolAddress((void**)&nT,   g_nT);
    cudaGetSymbolAddress((void**)&wqkv, g_wqkv);
    cudaGetSymbolAddress((void**)&wout, g_wout);
    cudaGetSymbolAddress((void**)&netT, g_netT);

    prep_kernel<<<1280, 256>>>(x, gn_w, gn_b, qkv_w, out_w);
    gemm_qkv<<<dim3(12, 8, BATCH), 256>>>(nT, wqkv, qkv_b);
    flash_kernel<<<dim3(16, NHEAD), 128>>>();
    gemm_out<<<dim3(8, 8, BATCH), 128>>>(wout, netT, out_b, x, out);
}

// round 11
// speedup vs baseline: 1.0856x; 1.0856x over previous
#include <cuda_runtime.h>
#include <cuda_fp16.h>
#include <cstddef>
#include <cstdint>

#define BATCH 8
#define CH    512
#define TOK   1024
#define HEADS 8
#define HD    64
#define NHEAD (BATCH*HEADS)   // 64
#define GROUPS 32
#define CPG   16

#define QSCALE 0.1803368801111204f   // 0.125 * log2(e)

// ---------------- scratch (__device__ globals; alloc-free rule) -------------
__device__ __align__(16) __half g_nT  [(size_t)BATCH*TOK*CH];    // [b][t][c]
__device__ __align__(16) __half g_wqkv[(size_t)3*CH*CH];         // [och][c]
__device__ __align__(16) __half g_wout[(size_t)CH*CH];           // [och][c]
__device__ __align__(16) __half g_q   [(size_t)NHEAD*TOK*HD];    // [head][t][c]  (x QSCALE)
__device__ __align__(16) __half g_k   [(size_t)NHEAD*TOK*HD];    // [head][s][c]
__device__ __align__(16) __half g_v   [(size_t)NHEAD*HD*TOK];    // [head][c][s]
__device__ __align__(16) __half g_netT[(size_t)BATCH*TOK*CH];    // [b][t][c]

// ---------------- helpers ---------------------------------------------------
__device__ __forceinline__ void mma_f16(float* c, const uint32_t* a, const uint32_t* b)
{
    asm volatile(
        "mma.sync.aligned.m16n8k16.row.col.f32.f16.f16.f32 "
        "{%0,%1,%2,%3},{%4,%5,%6,%7},{%8,%9},{%0,%1,%2,%3};"
        : "+f"(c[0]), "+f"(c[1]), "+f"(c[2]), "+f"(c[3])
        : "r"(a[0]), "r"(a[1]), "r"(a[2]), "r"(a[3]), "r"(b[0]), "r"(b[1]));
}

__device__ __forceinline__ void ldsm4(uint32_t* r, uint32_t addr)
{
    asm volatile("ldmatrix.sync.aligned.m8n8.x4.shared.b16 {%0,%1,%2,%3}, [%4];"
        : "=r"(r[0]), "=r"(r[1]), "=r"(r[2]), "=r"(r[3]) : "r"(addr));
}

// P = 2^(half2(lo,hi) - 2): cvt f32x2->f16x2, shift (cancels in O/l), packed ex2
__device__ __forceinline__ uint32_t h2p(float lo, float hi)
{
    uint32_t d;
    asm("cvt.rn.f16x2.f32 %0, %1, %2;" : "=r"(d) : "f"(hi), "f"(lo));
    asm("add.f16x2 %0, %0, %1;" : "+r"(d) : "r"(0xC000C000u));   // (-2,-2)
    asm("ex2.approx.f16x2 %0, %0;" : "+r"(d));
    return d;
}

__device__ __forceinline__ void cp16(void* s, const void* g)
{
    uint32_t sa = (uint32_t)__cvta_generic_to_shared(s);
    asm volatile("cp.async.cg.shared.global [%0], [%1], 16;\n" :: "r"(sa), "l"(g));
}
#define CP_COMMIT() asm volatile("cp.async.commit_group;\n" ::: "memory")
#define CP_WAIT0()  asm volatile("cp.async.wait_group 0;\n" ::: "memory")

// ---------------------------------------------------------------------------
// Kernel 1: fused prep. Blocks 0..255: GroupNorm -> g_nT (transposed, half),
// sync-free transform. Blocks 256..1279: weight fp32->fp16 conversion.
// ---------------------------------------------------------------------------
__global__ void prep_kernel(const float* __restrict__ x,
                            const float* __restrict__ w,
                            const float* __restrict__ bb,
                            const float* __restrict__ qkvw,
                            const float* __restrict__ outw)
{
    int tid = threadIdx.x;
    if (blockIdx.x >= 256) {
        int i = (blockIdx.x - 256) * 256 + tid;
        const int N1 = 3*CH*CH/4;
        const int N2 = CH*CH/4;
        if (i < N1) {
            float4 v = *(const float4*)(qkvw + (size_t)i*4);
            __half* d = g_wqkv + (size_t)i*4;
            d[0]=__float2half_rn(v.x); d[1]=__float2half_rn(v.y);
            d[2]=__float2half_rn(v.z); d[3]=__float2half_rn(v.w);
        } else if (i < N1 + N2) {
            int j = i - N1;
            float4 v = *(const float4*)(outw + (size_t)j*4);
            __half* d = g_wout + (size_t)j*4;
            d[0]=__float2half_rn(v.x); d[1]=__float2half_rn(v.y);
            d[2]=__float2half_rn(v.z); d[3]=__float2half_rn(v.w);
        }
        return;
    }

    int blk = blockIdx.x;
    int b = blk >> 5, gg = blk & 31;
    const float* src = x + ((size_t)b*CH + gg*CPG) * TOK;
    const int N = CPG * TOK;   // 16384

    float s = 0.f, ss = 0.f;
    for (int i = tid*4; i < N; i += 256*4) {
        float4 v = *(const float4*)(src + i);
        s  += v.x + v.y + v.z + v.w;
        ss += v.x*v.x + v.y*v.y + v.z*v.z + v.w*v.w;
    }
    for (int o = 16; o; o >>= 1) {
        s  += __shfl_down_sync(~0u, s,  o);
        ss += __shfl_down_sync(~0u, ss, o);
    }
    __shared__ float shs[8], shq[8];
    __shared__ float f_mu, f_rstd;
    if ((tid & 31) == 0) { shs[tid>>5] = s; shq[tid>>5] = ss; }
    __syncthreads();
    if (tid == 0) {
        float ts = 0.f, tq = 0.f;
        #pragma unroll
        for (int i = 0; i < 8; i++) { ts += shs[i]; tq += shq[i]; }
        float mu  = ts / N;
        f_mu = mu;
        f_rstd = rsqrtf(tq / N - mu*mu + 1e-5f);
    }
    __syncthreads();
    float mu = f_mu, rstd = f_rstd;

    // sync-free normalize+transpose: thread owns (token lane, c-quad)
    int tl = tid >> 2;            // 0..63
    int c4 = (tid & 3) * 4;
    float scw[4], scb[4];
    #pragma unroll
    for (int i = 0; i < 4; i++) {
        scw[i] = w[gg*CPG + c4 + i] * rstd;
        scb[i] = bb[gg*CPG + c4 + i] - mu * scw[i];
    }
    const float* s0 = src + (size_t)c4*TOK;
    #pragma unroll 4
    for (int t0 = 0; t0 < TOK; t0 += 64) {
        int t = t0 + tl;
        float v0 = s0[t];
        float v1 = s0[TOK + t];
        float v2 = s0[2*TOK + t];
        float v3 = s0[3*TOK + t];
        __half2 h0 = __floats2half2_rn(v0*scw[0]+scb[0], v1*scw[1]+scb[1]);
        __half2 h1 = __floats2half2_rn(v2*scw[2]+scb[2], v3*scw[3]+scb[3]);
        __half* dst = g_nT + ((size_t)b*TOK + t)*CH + gg*CPG + c4;
        *(__half2*)(dst)   = h0;
        *(__half2*)(dst+2) = h1;
    }
}

// ---------------------------------------------------------------------------
// Kernel 2/4: half GEMM, C[m][n] = sum_k A[m][k] * B[n][k], K=512.
// 128x128 block tile, 8 warps; 2-buffer cp.async, ONE sync/iter; ldmatrix.
// ---------------------------------------------------------------------------
template<int MODE>
__global__ void __launch_bounds__(256)
gemm_h(const __half* __restrict__ Abase, const __half* __restrict__ Bbase,
       const float* __restrict__ bias, const float* __restrict__ res,
       float* __restrict__ Cout)
{
    __shared__ __align__(16) __half As[2][128][40];
    __shared__ __align__(16) __half Bs[2][128][40];

    int bz = blockIdx.z;
    const __half* A = Abase + (MODE == 0 ? (size_t)bz*TOK*CH : 0);
    const __half* B = Bbase + (MODE == 1 ? (size_t)bz*TOK*CH : 0);

    int m0 = blockIdx.y * 128, n0 = blockIdx.x * 128;
    int tid = threadIdx.x, wid = tid >> 5, lane = tid & 31;
    int g = lane >> 2, tg = lane & 3;
    int wm = wid & 3, wn = wid >> 2;

    int lr = tid >> 2;
    int lc = (tid & 3) * 8;

    uint32_t sA = (uint32_t)__cvta_generic_to_shared(&As[0][0][0]);
    uint32_t sB = (uint32_t)__cvta_generic_to_shared(&Bs[0][0][0]);
    const int BUFB = 128*40*2;          // bytes per buffer
    // ldmatrix lane addressing
    int a_row = (lane & 15);            // + wm*32 + i*16
    int a_col = (lane >> 4) << 3;       // + kk*16
    int b_row = (lane & 7) + ((lane >> 3) & 1) * 8;   // + wn*64 + jp*16
    int b_col = (lane >> 4) << 3;       // + kk*16

    cp16(&As[0][lr   ][lc], A + (size_t)(m0+lr   )*CH + lc);
    cp16(&As[0][lr+64][lc], A + (size_t)(m0+lr+64)*CH + lc);
    cp16(&Bs[0][lr   ][lc], B + (size_t)(n0+lr   )*CH + lc);
    cp16(&Bs[0][lr+64][lc], B + (size_t)(n0+lr+64)*CH + lc);
    CP_COMMIT();

    float acc[2][8][4] = {};

    for (int ks = 0; ks < 16; ks++) {
        int buf = ks & 1;
        CP_WAIT0();
        __syncthreads();
        if (ks + 1 < 16) {
            int k1 = (ks+1) * 32;
            cp16(&As[buf^1][lr   ][lc], A + (size_t)(m0+lr   )*CH + k1 + lc);
            cp16(&As[buf^1][lr+64][lc], A + (size_t)(m0+lr+64)*CH + k1 + lc);
            cp16(&Bs[buf^1][lr   ][lc], B + (size_t)(n0+lr   )*CH + k1 + lc);
            cp16(&Bs[buf^1][lr+64][lc], B + (size_t)(n0+lr+64)*CH + k1 + lc);
            CP_COMMIT();
        }
        #pragma unroll
        for (int kk = 0; kk < 2; kk++) {
            uint32_t af[2][4], bf[8][2];
            #pragma unroll
            for (int i = 0; i < 2; i++) {
                int row = wm*32 + i*16 + a_row;
                int col = kk*16 + a_col;
                ldsm4(af[i], sA + buf*BUFB + row*80 + col*2);
            }
            #pragma unroll
            for (int jp = 0; jp < 4; jp++) {
                int row = wn*64 + jp*16 + b_row;
                int col = kk*16 + b_col;
                uint32_t r[4];
                ldsm4(r, sB + buf*BUFB + row*80 + col*2);
                bf[2*jp  ][0] = r[0]; bf[2*jp  ][1] = r[2];
                bf[2*jp+1][0] = r[1]; bf[2*jp+1][1] = r[3];
            }
            #pragma unroll
            for (int i = 0; i < 2; i++)
                #pragma unroll
                for (int j = 0; j < 8; j++)
                    mma_f16(acc[i][j], af[i], bf[j]);
        }
    }

    if (MODE == 0) {
        #pragma unroll
        for (int j = 0; j < 8; j++) {
            int n = n0 + wn*64 + j*8 + tg*2;      // och
            float bi0 = bias[n], bi1 = bias[n+1];
            int hh = n / 192, r = n % 192;
            #pragma unroll
            for (int i = 0; i < 2; i++) {
                int t = m0 + wm*32 + i*16 + g;
                float v00 = acc[i][j][0]+bi0, v01 = acc[i][j][1]+bi1;
                float v10 = acc[i][j][2]+bi0, v11 = acc[i][j][3]+bi1;
                size_t hb = (size_t)(bz*HEADS + hh);
                if (r < 64) {
                    v00*=QSCALE; v01*=QSCALE; v10*=QSCALE; v11*=QSCALE;
                    __half* q = g_q + (hb*TOK)*HD + r;
                    *(__half2*)(q + (size_t)t    *HD) = __floats2half2_rn(v00, v01);
                    *(__half2*)(q + (size_t)(t+8)*HD) = __floats2half2_rn(v10, v11);
                } else if (r < 128) {
                    __half* k = g_k + (hb*TOK)*HD + (r-64);
                    *(__half2*)(k + (size_t)t    *HD) = __floats2half2_rn(v00, v01);
                    *(__half2*)(k + (size_t)(t+8)*HD) = __floats2half2_rn(v10, v11);
                } else {
                    int cc = r - 128;
                    __half* v = g_v + (hb*HD + cc)*TOK;
                    v[t]         = __float2half_rn(v00);
                    v[TOK + t]   = __float2half_rn(v01);
                    v[t+8]       = __float2half_rn(v10);
                    v[TOK + t+8] = __float2half_rn(v11);
                }
            }
        }
    } else {
        #pragma unroll
        for (int j = 0; j < 8; j++) {
            int n = n0 + wn*64 + j*8 + tg*2;
            #pragma unroll
            for (int i = 0; i < 2; i++) {
                int m = m0 + wm*32 + i*16 + g;
                float ob0 = bias[m], ob1 = bias[m+8];
                size_t o0 = ((size_t)bz*CH + m)*TOK + n;
                size_t o1 = ((size_t)bz*CH + m+8)*TOK + n;
                float2 r0 = *(const float2*)(res + o0);
                float2 r1 = *(const float2*)(res + o1);
                float2 w0 = { acc[i][j][0]+ob0+r0.x, acc[i][j][1]+ob0+r0.y };
                float2 w1 = { acc[i][j][2]+ob1+r1.x, acc[i][j][3]+ob1+r1.y };
                *(float2*)(Cout + o0) = w0;
                *(float2*)(Cout + o1) = w1;
            }
        }
    }
}

// ---------------------------------------------------------------------------
// Kernel 3: flash attention. Block = (head, 64 q-rows), 128 thr / 4 warps.
// ldmatrix fragment loads; static-shift f16x2 softmax; ones-column row sums;
// 2-buffer cp.async, ONE sync per s-iteration.
// ---------------------------------------------------------------------------
__global__ void __launch_bounds__(128) flash_kernel()
{
    int head = blockIdx.y;
    int b = head >> 3, h = head & 7;
    int t0 = blockIdx.x * 64;
    const __half* Qg = g_q + ((size_t)head*TOK + t0)*HD;
    const __half* Kg = g_k + (size_t)head*TOK*HD;
    const __half* Vg = g_v + (size_t)head*HD*TOK;

    __shared__ __align__(16) __half Qs[64][72];
    __shared__ __align__(16) __half Ks[2][64][72];
    __shared__ __align__(16) __half Vs[2][64][72];

    int tid = threadIdx.x, wid = tid >> 5, lane = tid & 31;

    uint32_t sQ = (uint32_t)__cvta_generic_to_shared(&Qs[0][0]);
    uint32_t sK = (uint32_t)__cvta_generic_to_shared(&Ks[0][0][0]);
    uint32_t sV = (uint32_t)__cvta_generic_to_shared(&Vs[0][0][0]);
    const int BUFB = 64*72*2;
    int a_row = (lane & 15);
    int a_col = (lane >> 4) << 3;
    int b_row = (lane & 7) + ((lane >> 3) & 1) * 8;
    int b_col = (lane >> 4) << 3;

    #pragma unroll
    for (int p = 0; p < 4; p++) {
        int u = tid + p*128;
        int r = u >> 3, cg = (u & 7) * 8;
        *(uint4*)&Qs[r][cg] = *(const uint4*)(Qg + (size_t)r*HD + cg);
    }
    #pragma unroll
    for (int p = 0; p < 4; p++) {
        int u = tid + p*128;
        int r = u >> 3, cg = (u & 7) * 8;
        cp16(&Ks[0][r][cg], Kg + (size_t)r*HD + cg);
        cp16(&Vs[0][r][cg], Vg + (size_t)r*TOK + cg);
    }
    CP_COMMIT();
    __syncthreads();

    uint32_t aq[4][4];
    #pragma unroll
    for (int kk = 0; kk < 4; kk++) {
        int row = wid*16 + a_row;
        int col = kk*16 + a_col;
        ldsm4(aq[kk], sQ + row*144 + col*2);
    }

    const uint32_t ones2 = 0x3C003C00u;    // half2(1,1)
    float o[8][4] = {};
    float ol[4] = {};                      // row-sum accumulator (ones column)

    for (int it = 0; it < 16; it++) {
        int buf = it & 1;
        CP_WAIT0();
        __syncthreads();
        if (it + 1 < 16) {
            int s1 = (it+1)*64;
            #pragma unroll
            for (int p = 0; p < 4; p++) {
                int u = tid + p*128;
                int r = u >> 3, cg = (u & 7) * 8;
                cp16(&Ks[buf^1][r][cg], Kg + (size_t)(s1+r)*HD + cg);
                cp16(&Vs[buf^1][r][cg], Vg + (size_t)r*TOK + s1 + cg);
            }
            CP_COMMIT();
        }

        // S = Q K^T  (log2 domain, pre-scaled)
        float sc[8][4] = {};
        #pragma unroll
        for (int kk = 0; kk < 4; kk++) {
            int col = kk*16 + b_col;
            #pragma unroll
            for (int jp = 0; jp < 4; jp++) {
                int row = jp*16 + b_row;
                uint32_t r[4];
                ldsm4(r, sK + buf*BUFB + row*144 + col*2);
                uint32_t bf0[2] = { r[0], r[2] };
                uint32_t bf1[2] = { r[1], r[3] };
                mma_f16(sc[2*jp  ], aq[kk], bf0);
                mma_f16(sc[2*jp+1], aq[kk], bf1);
            }
        }

        // P = 2^(S-2) in packed half2 (shift cancels exactly in O/l)
        uint32_t ph[8][2];
        #pragma unroll
        for (int j = 0; j < 8; j++) {
            ph[j][0] = h2p(sc[j][0], sc[j][1]);   // row g
            ph[j][1] = h2p(sc[j][2], sc[j][3]);   // row g+8
        }

        // O += P V ; ol += P * ones
        #pragma unroll
        for (int i = 0; i < 4; i++) {
            uint32_t ap[4];
            ap[0] = ph[2*i  ][0];
            ap[1] = ph[2*i  ][1];
            ap[2] = ph[2*i+1][0];
            ap[3] = ph[2*i+1][1];
            int col = i*16 + b_col;
            #pragma unroll
            for (int jp = 0; jp < 4; jp++) {
                int row = jp*16 + b_row;
                uint32_t r[4];
                ldsm4(r, sV + buf*BUFB + row*144 + col*2);
                uint32_t bf0[2] = { r[0], r[2] };
                uint32_t bf1[2] = { r[1], r[3] };
                mma_f16(o[2*jp  ], ap, bf0);
                mma_f16(o[2*jp+1], ap, bf1);
            }
            uint32_t bo[2] = { ones2, ones2 };
            mma_f16(ol, ap, bo);
        }
    }

    int g = lane >> 2, tg = lane & 3;
    float inv0 = 1.f / ol[0], inv1 = 1.f / ol[2];
    int t = t0 + wid*16 + g;
    size_t rowbase = (size_t)b*TOK;
    #pragma unroll
    for (int jc = 0; jc < 8; jc++) {
        int cc = h*HD + jc*8 + tg*2;
        *(__half2*)&g_netT[(rowbase + t  )*CH + cc] =
            __floats2half2_rn(o[jc][0]*inv0, o[jc][1]*inv0);
        *(__half2*)&g_netT[(rowbase + t+8)*CH + cc] =
            __floats2half2_rn(o[jc][2]*inv1, o[jc][3]*inv1);
    }
}

// ---------------------------------------------------------------------------
extern "C" void kernel_launch(void* const* d_in, const int* in_sizes, int n_in,
                              void* d_out, int out_size)
{
    const float* x     = (const float*)d_in[0];
    const float* gn_w  = (const float*)d_in[1];
    const float* gn_b  = (const float*)d_in[2];
    const float* qkv_w = (const float*)d_in[3];
    const float* qkv_b = (const float*)d_in[4];
    const float* out_w = (const float*)d_in[5];
    const float* out_b = (const float*)d_in[6];
    float* out = (float*)d_out;

    __half *nT, *wqkv, *wout, *netT;
    cudaGetSymbolAddress((void**)&nT,   g_nT);
    cudaGetSymbolAddress((void**)&wqkv, g_wqkv);
    cudaGetSymbolAddress((void**)&wout, g_wout);
    cudaGetSymbolAddress((void**)&netT, g_netT);

    prep_kernel<<<1280, 256>>>(x, gn_w, gn_b, qkv_w, out_w);
    gemm_h<0><<<dim3(12, 8, BATCH), 256>>>(nT, wqkv, qkv_b, nullptr, nullptr);
    flash_kernel<<<dim3(16, NHEAD), 128>>>();
    gemm_h<1><<<dim3(8, 4, BATCH), 256>>>(wout, netT, out_b, x, out);
}